// round 16
// baseline (speedup 1.0000x reference)
#include <cuda_runtime.h>
#include <cuda_bf16.h>

// CrossNet: B=500000, D=128, L=4.   out = alpha_L * x0 + beta_L
//   d_l = w_l·x0 ; alpha_{l+1} = alpha_l*(1+d_l) + c_l ; c_l = w_l·beta_l
//
// R16: R15 (best: 78.6us harness / 74.0 ncu, DRAM 77.6%) with the register
// budget tightened: __launch_bounds__(128, 9) caps at 56 regs so 9 blocks/SM
// fit the 64K register file (R15's 64 regs x 8 blocks was exactly RF-bound at
// 41% occ). Live-set analysis says 56 fits without spills; +12.5% resident
// warps on an unchanged memory mix.

#define CN_L  4
#define CN_D  128

__global__ __launch_bounds__(128, 9) void crossnet_kernel(
    const float4* __restrict__ x,     // inputs  [B,128] as float4 [B,32]
    const float4* __restrict__ w4,    // kernels [L,128] as float4
    const float4* __restrict__ b4,    // biases
    float4*       __restrict__ out,
    int B)
{
    __shared__ float4 ws[CN_L * 32];  // weights (global layout mirrored)
    __shared__ float4 sbeta[32];      // beta_L
    __shared__ float  sc[CN_L];       // c_l

    const int tid  = threadIdx.x;
    const int wid  = tid >> 5;                     // warp in block (0..3)
    const int lane = tid & 31;
    const int sub  = lane >> 3;                    // row within group (0..3)
    const int li   = lane & 7;                     // lane within 8-lane team

    const int warp  = (blockIdx.x << 2) + wid;     // 4 warps/block
    const int baseA = (warp * 8 + sub) * 32 + li;  // float4 index, < 16M
    const int baseB = baseA + 4 * 32;

    // stage weights (each of the 128 threads loads exactly one float4)
    ws[tid] = w4[tid];

    float4 xa[4], xb[4];
    if (wid != 0) {
        // warps 1-3: front-batch the 8 DRAM row loads BEFORE the barrier,
        // so warp 0's prologue below hides under this latency.
#pragma unroll
        for (int i = 0; i < 4; ++i) xa[i] = __ldcs(&x[baseA + i * 8]);
#pragma unroll
        for (int i = 0; i < 4; ++i) xb[i] = __ldcs(&x[baseB + i * 8]);
    } else {
        // warp 0: beta_L and c_l with all 8 const loads front-batched
        float4 bl[CN_L], wl[CN_L];
#pragma unroll
        for (int l = 0; l < CN_L; ++l) bl[l] = __ldg(&b4[l * 32 + lane]);
#pragma unroll
        for (int l = 0; l < CN_L; ++l) wl[l] = __ldg(&w4[l * 32 + lane]);

        float4 bt = make_float4(0.f, 0.f, 0.f, 0.f);
        float cp[CN_L];
#pragma unroll
        for (int l = 0; l < CN_L; ++l) {
            float p = wl[l].x * bt.x;
            p = fmaf(wl[l].y, bt.y, p);
            p = fmaf(wl[l].z, bt.z, p);
            p = fmaf(wl[l].w, bt.w, p);
            cp[l] = p;
            bt.x += bl[l].x; bt.y += bl[l].y;
            bt.z += bl[l].z; bt.w += bl[l].w;
        }
#pragma unroll
        for (int off = 16; off > 0; off >>= 1) {
#pragma unroll
            for (int l = 0; l < CN_L; ++l)
                cp[l] += __shfl_xor_sync(0xffffffffu, cp[l], off);
        }
        sbeta[lane] = bt;
        if (lane == 0) {
#pragma unroll
            for (int l = 0; l < CN_L; ++l) sc[l] = cp[l];
        }
        // warp 0's own row loads (after prologue to bound register liveness)
#pragma unroll
        for (int i = 0; i < 4; ++i) xa[i] = __ldcs(&x[baseA + i * 8]);
#pragma unroll
        for (int i = 0; i < 4; ++i) xb[i] = __ldcs(&x[baseB + i * 8]);
    }
    __syncthreads();

    // partial dots d_l = w_l·x0 over this lane's 16 cols (weights from smem)
    float pa[CN_L], pb[CN_L];
#pragma unroll
    for (int l = 0; l < CN_L; ++l) {
        float qa = 0.f, qb = 0.f;
#pragma unroll
        for (int i = 0; i < 4; ++i) {
            const float4 wv = ws[l * 32 + i * 8 + li];
            qa = fmaf(wv.x, xa[i].x, qa);  qb = fmaf(wv.x, xb[i].x, qb);
            qa = fmaf(wv.y, xa[i].y, qa);  qb = fmaf(wv.y, xb[i].y, qb);
            qa = fmaf(wv.z, xa[i].z, qa);  qb = fmaf(wv.z, xb[i].z, qb);
            qa = fmaf(wv.w, xa[i].w, qa);  qb = fmaf(wv.w, xb[i].w, qb);
        }
        pa[l] = qa; pb[l] = qb;
    }
    // 3-level butterfly within 8-lane teams; each SHFL serves 4 rows
#pragma unroll
    for (int off = 1; off < 8; off <<= 1) {
#pragma unroll
        for (int l = 0; l < CN_L; ++l) {
            pa[l] += __shfl_xor_sync(0xffffffffu, pa[l], off);
            pb[l] += __shfl_xor_sync(0xffffffffu, pb[l], off);
        }
    }

    // scalar alpha recurrences
    float aA = 1.0f, aB = 1.0f;
#pragma unroll
    for (int l = 0; l < CN_L; ++l) {
        const float cl = sc[l];
        aA = fmaf(aA, pa[l], aA + cl);
        aB = fmaf(aB, pb[l], aB + cl);
    }

    // epilogue: out = a * x0 + beta
#pragma unroll
    for (int i = 0; i < 4; ++i) {
        const float4 bt = sbeta[i * 8 + li];
        float4 o;
        o.x = fmaf(xa[i].x, aA, bt.x);
        o.y = fmaf(xa[i].y, aA, bt.y);
        o.z = fmaf(xa[i].z, aA, bt.z);
        o.w = fmaf(xa[i].w, aA, bt.w);
        __stcs(&out[baseA + i * 8], o);
        o.x = fmaf(xb[i].x, aB, bt.x);
        o.y = fmaf(xb[i].y, aB, bt.y);
        o.z = fmaf(xb[i].z, aB, bt.z);
        o.w = fmaf(xb[i].w, aB, bt.w);
        __stcs(&out[baseB + i * 8], o);
    }
}

extern "C" void kernel_launch(void* const* d_in, const int* in_sizes, int n_in,
                              void* d_out, int out_size)
{
    const float* x = (const float*)d_in[0];   // inputs  [B,128]
    const float* w = (const float*)d_in[1];   // kernels [L,128,1]
    const float* b = (const float*)d_in[2];   // biases  [L,128,1]
    float* out = (float*)d_out;

    const int B = in_sizes[0] / CN_D;          // 500000
    const int warps = (B + 7) / 8;             // 62500 (exact)
    const int grid  = (warps + 3) / 4;         // 15625 (exact, 4 warps/block)

    crossnet_kernel<<<grid, 128>>>(
        reinterpret_cast<const float4*>(x),
        reinterpret_cast<const float4*>(w),
        reinterpret_cast<const float4*>(b),
        reinterpret_cast<float4*>(out), B);
}

// round 17
// speedup vs baseline: 1.0037x; 1.0037x over previous
#include <cuda_runtime.h>
#include <cuda_bf16.h>

// CrossNet: B=500000, D=128, L=4.   out = alpha_L * x0 + beta_L
//   d_l = w_l·x0 ; alpha_{l+1} = alpha_l*(1+d_l) + c_l ; c_l = w_l·beta_l
//
// R17: R16 structure (8-lane row teams, 3 SHFL/row, 8 rows/warp, 8 front-
// batched 128b loads/lane, 128-thr blocks, grid=15625 exact, hidden prologue)
// with the arithmetic datapath moved to packed f32x2 (FFMA2 via PTX
// fma.rn.f32x2 — sm_103a native, ptxas never auto-fuses). Dot FMAs halve
// (128 -> 64 instr/lane), epilogue halves; x/weights/beta live as u64 pairs
// end-to-end so no packing movs. Targets instruction-issue and power (the
// sustained-replay throttle that keeps harness ~5us above ncu time).

#define CN_L  4
#define CN_D  128

__device__ __forceinline__ unsigned long long ffma2(unsigned long long a,
                                                    unsigned long long b,
                                                    unsigned long long c) {
    unsigned long long d;
    asm("fma.rn.f32x2 %0, %1, %2, %3;" : "=l"(d) : "l"(a), "l"(b), "l"(c));
    return d;
}
__device__ __forceinline__ unsigned long long pack2(float lo, float hi) {
    unsigned long long r;
    asm("mov.b64 %0, {%1, %2};" : "=l"(r) : "f"(lo), "f"(hi));
    return r;
}
__device__ __forceinline__ float2 unpack2(unsigned long long v) {
    float2 f;
    asm("mov.b64 {%0, %1}, %2;" : "=f"(f.x), "=f"(f.y) : "l"(v));
    return f;
}

__global__ __launch_bounds__(128, 9) void crossnet_kernel(
    const ulonglong2* __restrict__ x,    // [B,128] fp32 as packed-pair vec16B
    const ulonglong2* __restrict__ w4,   // kernels [L,128] packed
    const float4*     __restrict__ b4,   // biases (float view for prologue)
    ulonglong2*       __restrict__ out,
    int B)
{
    __shared__ ulonglong2 ws[CN_L * 32];   // weights, packed pairs
    __shared__ ulonglong2 sbeta[32];       // beta_L, packed pairs
    __shared__ float      sc[CN_L];        // c_l

    const int tid  = threadIdx.x;
    const int wid  = tid >> 5;                     // warp in block (0..3)
    const int lane = tid & 31;
    const int sub  = lane >> 3;                    // row within group (0..3)
    const int li   = lane & 7;                     // lane within 8-lane team

    const int warp  = (blockIdx.x << 2) + wid;     // 4 warps/block
    const int baseA = (warp * 8 + sub) * 32 + li;  // 16B-vector index
    const int baseB = baseA + 4 * 32;

    // stage weights (each thread loads exactly one 16B vector)
    ws[tid] = w4[tid];

    ulonglong2 xa[4], xb[4];
    if (wid != 0) {
        // warps 1-3: front-batch the 8 DRAM row loads BEFORE the barrier
#pragma unroll
        for (int i = 0; i < 4; ++i) xa[i] = __ldcs(&x[baseA + i * 8]);
#pragma unroll
        for (int i = 0; i < 4; ++i) xb[i] = __ldcs(&x[baseB + i * 8]);
    } else {
        // warp 0: beta_L and c_l, all 8 const loads front-batched (float path)
        const float4* w4f = reinterpret_cast<const float4*>(w4);
        float4 bl[CN_L], wl[CN_L];
#pragma unroll
        for (int l = 0; l < CN_L; ++l) bl[l] = __ldg(&b4[l * 32 + lane]);
#pragma unroll
        for (int l = 0; l < CN_L; ++l) wl[l] = __ldg(&w4f[l * 32 + lane]);

        float4 bt = make_float4(0.f, 0.f, 0.f, 0.f);
        float cp[CN_L];
#pragma unroll
        for (int l = 0; l < CN_L; ++l) {
            float p = wl[l].x * bt.x;
            p = fmaf(wl[l].y, bt.y, p);
            p = fmaf(wl[l].z, bt.z, p);
            p = fmaf(wl[l].w, bt.w, p);
            cp[l] = p;
            bt.x += bl[l].x; bt.y += bl[l].y;
            bt.z += bl[l].z; bt.w += bl[l].w;
        }
#pragma unroll
        for (int off = 16; off > 0; off >>= 1) {
#pragma unroll
            for (int l = 0; l < CN_L; ++l)
                cp[l] += __shfl_xor_sync(0xffffffffu, cp[l], off);
        }
        ulonglong2 btp;
        btp.x = pack2(bt.x, bt.y);
        btp.y = pack2(bt.z, bt.w);
        sbeta[lane] = btp;
        if (lane == 0) {
#pragma unroll
            for (int l = 0; l < CN_L; ++l) sc[l] = cp[l];
        }
        // warp 0's own row loads
#pragma unroll
        for (int i = 0; i < 4; ++i) xa[i] = __ldcs(&x[baseA + i * 8]);
#pragma unroll
        for (int i = 0; i < 4; ++i) xb[i] = __ldcs(&x[baseB + i * 8]);
    }
    __syncthreads();

    // packed partial dots d_l = w_l·x0 over this lane's 16 cols
    float pa[CN_L], pb[CN_L];
#pragma unroll
    for (int l = 0; l < CN_L; ++l) {
        unsigned long long qa = 0ull, qb = 0ull;   // (0.0f, 0.0f)
#pragma unroll
        for (int i = 0; i < 4; ++i) {
            const ulonglong2 wv = ws[l * 32 + i * 8 + li];
            qa = ffma2(wv.x, xa[i].x, qa);
            qb = ffma2(wv.x, xb[i].x, qb);
            qa = ffma2(wv.y, xa[i].y, qa);
            qb = ffma2(wv.y, xb[i].y, qb);
        }
        const float2 fa = unpack2(qa);
        const float2 fb = unpack2(qb);
        pa[l] = fa.x + fa.y;
        pb[l] = fb.x + fb.y;
    }
    // 3-level butterfly within 8-lane teams; each SHFL serves 4 rows
#pragma unroll
    for (int off = 1; off < 8; off <<= 1) {
#pragma unroll
        for (int l = 0; l < CN_L; ++l) {
            pa[l] += __shfl_xor_sync(0xffffffffu, pa[l], off);
            pb[l] += __shfl_xor_sync(0xffffffffu, pb[l], off);
        }
    }

    // scalar alpha recurrences
    float aA = 1.0f, aB = 1.0f;
#pragma unroll
    for (int l = 0; l < CN_L; ++l) {
        const float cl = sc[l];
        aA = fmaf(aA, pa[l], aA + cl);
        aB = fmaf(aB, pb[l], aB + cl);
    }
    const unsigned long long aA2 = pack2(aA, aA);
    const unsigned long long aB2 = pack2(aB, aB);

    // packed epilogue: out = a * x0 + beta
#pragma unroll
    for (int i = 0; i < 4; ++i) {
        const ulonglong2 bt = sbeta[i * 8 + li];
        ulonglong2 o;
        o.x = ffma2(xa[i].x, aA2, bt.x);
        o.y = ffma2(xa[i].y, aA2, bt.y);
        __stcs(&out[baseA + i * 8], o);
        o.x = ffma2(xb[i].x, aB2, bt.x);
        o.y = ffma2(xb[i].y, aB2, bt.y);
        __stcs(&out[baseB + i * 8], o);
    }
}

extern "C" void kernel_launch(void* const* d_in, const int* in_sizes, int n_in,
                              void* d_out, int out_size)
{
    const float* x = (const float*)d_in[0];   // inputs  [B,128]
    const float* w = (const float*)d_in[1];   // kernels [L,128,1]
    const float* b = (const float*)d_in[2];   // biases  [L,128,1]
    float* out = (float*)d_out;

    const int B = in_sizes[0] / CN_D;          // 500000
    const int warps = (B + 7) / 8;             // 62500 (exact)
    const int grid  = (warps + 3) / 4;         // 15625 (exact, 4 warps/block)

    crossnet_kernel<<<grid, 128>>>(
        reinterpret_cast<const ulonglong2*>(x),
        reinterpret_cast<const ulonglong2*>(w),
        reinterpret_cast<const float4*>(b),
        reinterpret_cast<ulonglong2*>(out), B);
}